// round 13
// baseline (speedup 1.0000x reference)
#include <cuda_runtime.h>
#include <cuda_bf16.h>
#include <cstdint>

#define Bdim 8
#define Wdim 4096
#define Rdim 128
#define Ddim 128
#define BLK  128
#define NBLK 32
#define NTHR 256

// ---------------------------------------------------------------------------
// Scratch (__device__ globals; allocation-free rule)
// ---------------------------------------------------------------------------
__device__ float g_ptab[129 * 128];   // ptab[i*128+r] = gamma_r^i
__device__ float g_ntab[128 * 128];   // ntab[j*128+r] = gamma_r^{-j}
__device__ float g_A[Bdim * NBLK * BLK * BLK];       // masked A[i][j]
__device__ float g_U[Bdim * NBLK * Ddim * Rdim];     // Ut layout [d][r]
__device__ float g_S[Bdim * NBLK * Ddim * Rdim];     // St layout [d][r]

// ---------------------------------------------------------------------------
// SMEM: DOUBLE-buffered bf16 tiles, k-chunk = 32.
// One buffer = 4 tiles x (128 rows x 80B) = 40960B. Two buffers = 81920B.
// 80B row stride: 16B-aligned ldmatrix rows, conflict-free phases.
// ---------------------------------------------------------------------------
#define CROWB   80
#define CTILEB  (128 * CROWB)           // 10240
#define T_AHI   0
#define T_ALO   CTILEB
#define T_BHI   (2 * CTILEB)
#define T_BLO   (3 * CTILEB)
#define TILBUF  (4 * CTILEB)            // 40960 per buffer
#define SMEM_TOTAL (2 * TILBUF)         // 81920 -> 2 CTAs/SM

__device__ __forceinline__ uint32_t smem_u32(const void* p) {
    uint32_t a;
    asm("{ .reg .u64 t; cvta.to.shared.u64 t, %1; cvt.u32.u64 %0, t; }" : "=r"(a) : "l"(p));
    return a;
}

__device__ __forceinline__ void split1(float a, unsigned short& h, unsigned short& l) {
    __nv_bfloat16 hb = __float2bfloat16(a);
    float rem = a - __bfloat162float(hb);
    __nv_bfloat16 lb = __float2bfloat16(rem);
    h = *(unsigned short*)&hb;
    l = *(unsigned short*)&lb;
}
__device__ __forceinline__ unsigned long long pack4(unsigned short a, unsigned short b,
                                                    unsigned short c, unsigned short d) {
    return (unsigned long long)a | ((unsigned long long)b << 16)
         | ((unsigned long long)c << 32) | ((unsigned long long)d << 48);
}

// ---------------------------------------------------------------------------
// Direct staging gmem -> bf16 hi/lo tiles (k-chunk 32)
// nat: tile[m][c] = src[m][kc+c] * (wt ? wt[(m+wrofs)*128 + kc+c] : 1)
// ---------------------------------------------------------------------------
__device__ __forceinline__ void stage_nat32(const float* __restrict__ src,
                                            const float* __restrict__ wt, int wrofs,
                                            int kc, char* hiT, char* loT, int tid) {
#pragma unroll
    for (int it = 0; it < 4; it++) {
        int t = tid + it * NTHR;            // 0..1023
        int row = t >> 3, c4 = (t & 7) << 2;
        float4 v = *(const float4*)(src + row * 128 + kc + c4);
        if (wt) {
            float4 w = *(const float4*)(wt + (row + wrofs) * 128 + kc + c4);
            v.x *= w.x; v.y *= w.y; v.z *= w.z; v.w *= w.w;
        }
        unsigned short h[4], l[4];
        split1(v.x, h[0], l[0]); split1(v.y, h[1], l[1]);
        split1(v.z, h[2], l[2]); split1(v.w, h[3], l[3]);
        int off = row * CROWB + c4 * 2;
        *(unsigned long long*)(hiT + off) = pack4(h[0], h[1], h[2], h[3]);
        *(unsigned long long*)(loT + off) = pack4(l[0], l[1], l[2], l[3]);
    }
}
// tr: tile[c][j-jc] = src[j][c] * (useW ? ptab[(127-j)*128+c] : 1), j in [jc,jc+32)
__device__ __forceinline__ void stage_tr32(const float* __restrict__ src, bool useW,
                                           int jc, char* hiT, char* loT, int tid) {
    int jblk = tid >> 5, c0 = (tid & 31) << 2;   // 8 jblks x 32 c-groups
    unsigned short hs[4][4], ls[4][4];
#pragma unroll
    for (int x = 0; x < 4; x++) {
        int j = jc + jblk * 4 + x;
        float4 v = *(const float4*)(src + j * 128 + c0);
        if (useW) {
            float4 w = *(const float4*)(g_ptab + (127 - j) * 128 + c0);
            v.x *= w.x; v.y *= w.y; v.z *= w.z; v.w *= w.w;
        }
        split1(v.x, hs[x][0], ls[x][0]); split1(v.y, hs[x][1], ls[x][1]);
        split1(v.z, hs[x][2], ls[x][2]); split1(v.w, hs[x][3], ls[x][3]);
    }
#pragma unroll
    for (int u = 0; u < 4; u++) {
        int off = (c0 + u) * CROWB + jblk * 8;
        *(unsigned long long*)(hiT + off) = pack4(hs[0][u], hs[1][u], hs[2][u], hs[3][u]);
        *(unsigned long long*)(loT + off) = pack4(ls[0][u], ls[1][u], ls[2][u], ls[3][u]);
    }
}

// ---------------------------------------------------------------------------
// mma.sync core: 8 warps, warp tile 32x64, fused bf16x3, k-chunk 32
// ---------------------------------------------------------------------------
__device__ __forceinline__ void ldsm_x4(uint32_t addr, uint32_t& r0, uint32_t& r1,
                                        uint32_t& r2, uint32_t& r3) {
    asm volatile("ldmatrix.sync.aligned.m8n8.x4.shared.b16 {%0,%1,%2,%3}, [%4];"
                 : "=r"(r0), "=r"(r1), "=r"(r2), "=r"(r3) : "r"(addr));
}
__device__ __forceinline__ void mma16816(float* c, const uint32_t a[4],
                                         uint32_t b0, uint32_t b1) {
    asm volatile("mma.sync.aligned.m16n8k16.row.col.f32.bf16.bf16.f32 "
                 "{%0,%1,%2,%3}, {%4,%5,%6,%7}, {%8,%9}, {%0,%1,%2,%3};"
                 : "+f"(c[0]), "+f"(c[1]), "+f"(c[2]), "+f"(c[3])
                 : "r"(a[0]), "r"(a[1]), "r"(a[2]), "r"(a[3]), "r"(b0), "r"(b1));
}

__device__ __forceinline__ void gemm32(const char* buf, int m0, int n0, int lane,
                                       float acc[2][8][4]) {
    uint32_t AHI = smem_u32(buf) + T_AHI;
    uint32_t ALO = smem_u32(buf) + T_ALO;
    uint32_t BHI = smem_u32(buf) + T_BHI;
    uint32_t BLO = smem_u32(buf) + T_BLO;
    int r = lane & 7, sub = lane >> 3;
    int aRow = (sub & 1) * 8 + r, aK = (sub >> 1) * 8;
    int bRow = (sub >> 1) * 8 + r, bK = (sub & 1) * 8;
#pragma unroll
    for (int ks = 0; ks < 2; ks++) {
        int k0 = ks * 16;
        uint32_t ahi[2][4], alo[2][4];
#pragma unroll
        for (int am = 0; am < 2; am++) {
            uint32_t base = (uint32_t)((m0 + am * 16 + aRow) * CROWB + (k0 + aK) * 2);
            ldsm_x4(AHI + base, ahi[am][0], ahi[am][1], ahi[am][2], ahi[am][3]);
            ldsm_x4(ALO + base, alo[am][0], alo[am][1], alo[am][2], alo[am][3]);
        }
#pragma unroll
        for (int g = 0; g < 4; g++) {
            uint32_t base = (uint32_t)((n0 + g * 16 + bRow) * CROWB + (k0 + bK) * 2);
            uint32_t bh0, bh1, bh2, bh3, bl0, bl1, bl2, bl3;
            ldsm_x4(BHI + base, bh0, bh1, bh2, bh3);
            ldsm_x4(BLO + base, bl0, bl1, bl2, bl3);
#pragma unroll
            for (int am = 0; am < 2; am++) {
                mma16816(acc[am][g * 2 + 0], ahi[am], bh0, bh1);
                mma16816(acc[am][g * 2 + 1], ahi[am], bh2, bh3);
                mma16816(acc[am][g * 2 + 0], ahi[am], bl0, bl1);
                mma16816(acc[am][g * 2 + 1], ahi[am], bl2, bl3);
                mma16816(acc[am][g * 2 + 0], alo[am], bh0, bh1);
                mma16816(acc[am][g * 2 + 1], alo[am], bh2, bh3);
            }
        }
    }
}

__device__ __forceinline__ void zero_acc(float acc[2][8][4]) {
#pragma unroll
    for (int am = 0; am < 2; am++)
#pragma unroll
        for (int g = 0; g < 8; g++)
#pragma unroll
            for (int e = 0; e < 4; e++) acc[am][g][e] = 0.f;
}

__device__ __forceinline__ void epilogue(float acc[2][8][4], float* __restrict__ dst,
                                         bool mask, int m0, int n0, int lane) {
    int t4 = lane >> 2, tp2 = (lane & 3) * 2;
#pragma unroll
    for (int am = 0; am < 2; am++) {
#pragma unroll
        for (int g = 0; g < 8; g++) {
            int col = n0 + g * 8 + tp2;
            int row0 = m0 + am * 16 + t4;
            float c0 = acc[am][g][0], c1 = acc[am][g][1];
            float c2 = acc[am][g][2], c3 = acc[am][g][3];
            if (mask) {
                if (row0 < col)         c0 = 0.f;
                if (row0 < col + 1)     c1 = 0.f;
                if (row0 + 8 < col)     c2 = 0.f;
                if (row0 + 8 < col + 1) c3 = 0.f;
            }
            *(float2*)(dst + row0 * 128 + col)       = make_float2(c0, c1);
            *(float2*)(dst + (row0 + 8) * 128 + col) = make_float2(c2, c3);
        }
    }
}

// ---------------------------------------------------------------------------
// Power tables
// ---------------------------------------------------------------------------
__global__ void pow_kernel(const float* __restrict__ gamma) {
    int r = threadIdx.x, row = blockIdx.x;
    float lg = logf(gamma[r]);
    if (row < 129) g_ptab[row * 128 + r] = expf((float)row * lg);
    else           g_ntab[(row - 129) * 128 + r] = expf(-(float)(row - 129) * lg);
}

// ---------------------------------------------------------------------------
// Phase 1 (merged, one wave): per CTA 8 chunks —
//   chunks 0-3: A = mask((QΓ)(KΓ')^T) -> g_A (epilogue mid-loop, no bubble)
//   chunks 4-7: Ut[d,r] = sum_j h[j,d] (k[j,r] g^(127-j)) -> g_U
// ---------------------------------------------------------------------------
__global__ __launch_bounds__(NTHR, 2) void matAU_kernel(const float* __restrict__ q,
                                                        const float* __restrict__ k,
                                                        const float* __restrict__ h) {
    extern __shared__ __align__(16) char smem[];
    int n = blockIdx.x, b = blockIdx.y;
    int tid = threadIdx.x, wid = tid >> 5, lane = tid & 31;
    int m0 = (wid & 3) * 32, n0 = (wid >> 2) * 64;

    const int in_base = (b * Wdim + n * BLK) * Rdim;
    float acc[2][8][4];
    zero_acc(acc);

    // stage A chunk 0 into buf0
    stage_nat32(q + in_base, g_ptab, 0, 0, smem + T_AHI, smem + T_ALO, tid);
    stage_nat32(k + in_base, g_ntab, 0, 0, smem + T_BHI, smem + T_BLO, tid);
    __syncthreads();

#pragma unroll
    for (int c = 0; c < 8; c++) {
        char* cur = smem + (c & 1) * TILBUF;
        gemm32(cur, m0, n0, lane, acc);
        if (c + 1 < 8) {
            int cn = c + 1;
            char* nxt = smem + (cn & 1) * TILBUF;
            if (cn < 4) {          // A chunks (contraction over r)
                int kc = cn * 32;
                stage_nat32(q + in_base, g_ptab, 0, kc, nxt + T_AHI, nxt + T_ALO, tid);
                stage_nat32(k + in_base, g_ntab, 0, kc, nxt + T_BHI, nxt + T_BLO, tid);
            } else {               // U chunks (contraction over j)
                int jc = (cn - 4) * 32;
                stage_tr32(h + in_base, false, jc, nxt + T_AHI, nxt + T_ALO, tid);
                stage_tr32(k + in_base, true,  jc, nxt + T_BHI, nxt + T_BLO, tid);
            }
        }
        __syncthreads();
        if (c == 3) {
            epilogue(acc, g_A + (b * NBLK + n) * (BLK * BLK), true, m0, n0, lane);
            zero_acc(acc);
        }
    }

    epilogue(acc, g_U + (b * NBLK + n) * (Ddim * Rdim), false, m0, n0, lane);
}

// ---------------------------------------------------------------------------
// Phase 2: prefix scan on [d][r] state, MLP-32 preload
// ---------------------------------------------------------------------------
__global__ void scan_kernel() {
    int gid = blockIdx.x * 256 + threadIdx.x;   // 131072
    int b = gid >> 14, dr = gid & 16383, r = dr & 127;
    float gdec = g_ptab[128 * 128 + r];         // gamma_r^128
    int base = b * NBLK * 16384 + dr;
    float u[NBLK];
#pragma unroll
    for (int nn = 0; nn < NBLK; nn++) u[nn] = g_U[base + nn * 16384];
    float s = 0.f;
#pragma unroll
    for (int nn = 0; nn < NBLK; nn++) {
        g_S[base + nn * 16384] = s;
        s = fmaf(s, gdec, u[nn]);
    }
}

// ---------------------------------------------------------------------------
// Phase 3: out = A @ H + (Q*g^(i+1)) @ St — one 8-chunk double-buffered loop
// ---------------------------------------------------------------------------
__global__ __launch_bounds__(NTHR, 2) void out_kernel(const float* __restrict__ q,
                                                      const float* __restrict__ h,
                                                      float* __restrict__ out) {
    extern __shared__ __align__(16) char smem[];
    int n = blockIdx.x, b = blockIdx.y;
    int tid = threadIdx.x, wid = tid >> 5, lane = tid & 31;
    int m0 = (wid & 3) * 32, n0 = (wid >> 2) * 64;

    const float* Ablk = g_A + (b * NBLK + n) * (BLK * BLK);
    const float* Sblk = g_S + (b * NBLK + n) * (Ddim * Rdim);
    const float* hblk = h + (b * Wdim + n * BLK) * Ddim;
    const float* qblk = q + (b * Wdim + n * BLK) * Rdim;

    float acc[2][8][4];
    zero_acc(acc);

    // stage chunk 0 (part 1, jc=0) into buf0
    stage_nat32(Ablk, (const float*)0, 0, 0, smem + T_AHI, smem + T_ALO, tid);
    stage_tr32(hblk, false, 0, smem + T_BHI, smem + T_BLO, tid);
    __syncthreads();

#pragma unroll
    for (int c = 0; c < 8; c++) {
        char* cur = smem + (c & 1) * TILBUF;
        gemm32(cur, m0, n0, lane, acc);
        if (c + 1 < 8) {
            int cn = c + 1;
            char* nxt = smem + (cn & 1) * TILBUF;
            if (cn < 4) {
                stage_nat32(Ablk, (const float*)0, 0, cn * 32, nxt + T_AHI, nxt + T_ALO, tid);
                stage_tr32(hblk, false, cn * 32, nxt + T_BHI, nxt + T_BLO, tid);
            } else {
                stage_nat32(qblk, g_ptab, 1, (cn - 4) * 32, nxt + T_AHI, nxt + T_ALO, tid);
                stage_nat32(Sblk, (const float*)0, 0, (cn - 4) * 32, nxt + T_BHI, nxt + T_BLO, tid);
            }
        }
        __syncthreads();
    }

    epilogue(acc, out + (b * Wdim + n * BLK) * Ddim, false, m0, n0, lane);
}

// ---------------------------------------------------------------------------
extern "C" void kernel_launch(void* const* d_in, const int* in_sizes, int n_in,
                              void* d_out, int out_size) {
    const float* q     = (const float*)d_in[0];
    const float* k     = (const float*)d_in[1];
    const float* h     = (const float*)d_in[2];
    const float* gamma = (const float*)d_in[3];
    float* out = (float*)d_out;

    cudaFuncSetAttribute(matAU_kernel, cudaFuncAttributeMaxDynamicSharedMemorySize, SMEM_TOTAL);
    cudaFuncSetAttribute(out_kernel,   cudaFuncAttributeMaxDynamicSharedMemorySize, SMEM_TOTAL);

    pow_kernel<<<257, 128>>>(gamma);
    matAU_kernel<<<dim3(NBLK, Bdim), NTHR, SMEM_TOTAL>>>(q, k, h);
    scan_kernel<<<512, 256>>>();
    out_kernel<<<dim3(NBLK, Bdim), NTHR, SMEM_TOTAL>>>(q, h, out);
}

// round 15
// speedup vs baseline: 1.0240x; 1.0240x over previous
#include <cuda_runtime.h>
#include <cuda_bf16.h>
#include <cstdint>

#define Bdim 8
#define Wdim 4096
#define Rdim 128
#define Ddim 128
#define BLK  128
#define NBLK 32
#define NTHR 256

// ---------------------------------------------------------------------------
// Scratch (__device__ globals; allocation-free rule)
// ---------------------------------------------------------------------------
__device__ float g_ptab[129 * 128];   // ptab[i*128+r] = gamma_r^i
__device__ float g_ntab[128 * 128];   // ntab[j*128+r] = gamma_r^{-j}
__device__ float g_A[Bdim * NBLK * BLK * BLK];       // masked A[i][j]
__device__ float g_U[Bdim * NBLK * Ddim * Rdim];     // Ut layout [d][r]
__device__ float g_S[Bdim * NBLK * Ddim * Rdim];     // St layout [d][r]

// ---------------------------------------------------------------------------
// Two tile geometries (both 16B-aligned row strides, measured-correct):
//  k32 path (matAU): CROWB32=80,  tile 10240B, double-buffered -> 81920B
//  k64 path (out):   CROWB64=144, tile 18432B, single buffer   -> 73728B
// ---------------------------------------------------------------------------
#define CROWB32   80
#define CTILEB32  (128 * CROWB32)          // 10240
#define TILBUF32  (4 * CTILEB32)           // 40960
#define SMEM_AU   (2 * TILBUF32)           // 81920 -> 2 CTAs/SM

#define CROWB64   144
#define CTILEB64  (128 * CROWB64)          // 18432
#define SMEM_OUT  (4 * CTILEB64)           // 73728 -> 2 CTAs/SM

__device__ __forceinline__ uint32_t smem_u32(const void* p) {
    uint32_t a;
    asm("{ .reg .u64 t; cvta.to.shared.u64 t, %1; cvt.u32.u64 %0, t; }" : "=r"(a) : "l"(p));
    return a;
}

__device__ __forceinline__ void split1(float a, unsigned short& h, unsigned short& l) {
    __nv_bfloat16 hb = __float2bfloat16(a);
    float rem = a - __bfloat162float(hb);
    __nv_bfloat16 lb = __float2bfloat16(rem);
    h = *(unsigned short*)&hb;
    l = *(unsigned short*)&lb;
}
__device__ __forceinline__ unsigned long long pack4(unsigned short a, unsigned short b,
                                                    unsigned short c, unsigned short d) {
    return (unsigned long long)a | ((unsigned long long)b << 16)
         | ((unsigned long long)c << 32) | ((unsigned long long)d << 48);
}

// ---------------------------------------------------------------------------
// k32 staging (matAU): direct gmem -> bf16 hi/lo tiles
// ---------------------------------------------------------------------------
__device__ __forceinline__ void stage_nat32(const float* __restrict__ src,
                                            const float* __restrict__ wt, int wrofs,
                                            int kc, char* hiT, char* loT, int tid) {
#pragma unroll
    for (int it = 0; it < 4; it++) {
        int t = tid + it * NTHR;            // 0..1023
        int row = t >> 3, c4 = (t & 7) << 2;
        float4 v = *(const float4*)(src + row * 128 + kc + c4);
        if (wt) {
            float4 w = *(const float4*)(wt + (row + wrofs) * 128 + kc + c4);
            v.x *= w.x; v.y *= w.y; v.z *= w.z; v.w *= w.w;
        }
        unsigned short h[4], l[4];
        split1(v.x, h[0], l[0]); split1(v.y, h[1], l[1]);
        split1(v.z, h[2], l[2]); split1(v.w, h[3], l[3]);
        int off = row * CROWB32 + c4 * 2;
        *(unsigned long long*)(hiT + off) = pack4(h[0], h[1], h[2], h[3]);
        *(unsigned long long*)(loT + off) = pack4(l[0], l[1], l[2], l[3]);
    }
}
__device__ __forceinline__ void stage_tr32(const float* __restrict__ src, bool useW,
                                           int jc, char* hiT, char* loT, int tid) {
    int jblk = tid >> 5, c0 = (tid & 31) << 2;   // 8 jblks x 32 c-groups
    unsigned short hs[4][4], ls[4][4];
#pragma unroll
    for (int x = 0; x < 4; x++) {
        int j = jc + jblk * 4 + x;
        float4 v = *(const float4*)(src + j * 128 + c0);
        if (useW) {
            float4 w = *(const float4*)(g_ptab + (127 - j) * 128 + c0);
            v.x *= w.x; v.y *= w.y; v.z *= w.z; v.w *= w.w;
        }
        split1(v.x, hs[x][0], ls[x][0]); split1(v.y, hs[x][1], ls[x][1]);
        split1(v.z, hs[x][2], ls[x][2]); split1(v.w, hs[x][3], ls[x][3]);
    }
#pragma unroll
    for (int u = 0; u < 4; u++) {
        int off = (c0 + u) * CROWB32 + jblk * 8;
        *(unsigned long long*)(hiT + off) = pack4(hs[0][u], hs[1][u], hs[2][u], hs[3][u]);
        *(unsigned long long*)(loT + off) = pack4(ls[0][u], ls[1][u], ls[2][u], ls[3][u]);
    }
}

// ---------------------------------------------------------------------------
// k64 staging (out_kernel)
// ---------------------------------------------------------------------------
__device__ __forceinline__ void stage_nat64(const float* __restrict__ src,
                                            const float* __restrict__ wt, int wrofs,
                                            int kc, char* hiT, char* loT, int tid) {
#pragma unroll
    for (int it = 0; it < 8; it++) {
        int t = tid + it * NTHR;            // 0..2047
        int row = t >> 4, c4 = (t & 15) << 2;
        float4 v = *(const float4*)(src + row * 128 + kc + c4);
        if (wt) {
            float4 w = *(const float4*)(wt + (row + wrofs) * 128 + kc + c4);
            v.x *= w.x; v.y *= w.y; v.z *= w.z; v.w *= w.w;
        }
        unsigned short h[4], l[4];
        split1(v.x, h[0], l[0]); split1(v.y, h[1], l[1]);
        split1(v.z, h[2], l[2]); split1(v.w, h[3], l[3]);
        int off = row * CROWB64 + c4 * 2;
        *(unsigned long long*)(hiT + off) = pack4(h[0], h[1], h[2], h[3]);
        *(unsigned long long*)(loT + off) = pack4(l[0], l[1], l[2], l[3]);
    }
}
__device__ __forceinline__ void stage_tr64(const float* __restrict__ src, bool useW,
                                           int jc, char* hiT, char* loT, int tid) {
#pragma unroll
    for (int it = 0; it < 2; it++) {
        int t = tid + it * NTHR;            // 0..511
        int jblk = t >> 5;                  // 0..15
        int c0   = (t & 31) << 2;           // 0..124
        int j0   = jc + jblk * 4;
        unsigned short hs[4][4], ls[4][4];
#pragma unroll
        for (int x = 0; x < 4; x++) {
            float4 v = *(const float4*)(src + (j0 + x) * 128 + c0);
            if (useW) {
                float4 w = *(const float4*)(g_ptab + (127 - (j0 + x)) * 128 + c0);
                v.x *= w.x; v.y *= w.y; v.z *= w.z; v.w *= w.w;
            }
            split1(v.x, hs[x][0], ls[x][0]); split1(v.y, hs[x][1], ls[x][1]);
            split1(v.z, hs[x][2], ls[x][2]); split1(v.w, hs[x][3], ls[x][3]);
        }
#pragma unroll
        for (int u = 0; u < 4; u++) {
            int off = (c0 + u) * CROWB64 + jblk * 8;
            *(unsigned long long*)(hiT + off) = pack4(hs[0][u], hs[1][u], hs[2][u], hs[3][u]);
            *(unsigned long long*)(loT + off) = pack4(ls[0][u], ls[1][u], ls[2][u], ls[3][u]);
        }
    }
}

// ---------------------------------------------------------------------------
// mma.sync core: 8 warps, warp tile 32x64, fused bf16x3
// ---------------------------------------------------------------------------
__device__ __forceinline__ void ldsm_x4(uint32_t addr, uint32_t& r0, uint32_t& r1,
                                        uint32_t& r2, uint32_t& r3) {
    asm volatile("ldmatrix.sync.aligned.m8n8.x4.shared.b16 {%0,%1,%2,%3}, [%4];"
                 : "=r"(r0), "=r"(r1), "=r"(r2), "=r"(r3) : "r"(addr));
}
__device__ __forceinline__ void mma16816(float* c, const uint32_t a[4],
                                         uint32_t b0, uint32_t b1) {
    asm volatile("mma.sync.aligned.m16n8k16.row.col.f32.bf16.bf16.f32 "
                 "{%0,%1,%2,%3}, {%4,%5,%6,%7}, {%8,%9}, {%0,%1,%2,%3};"
                 : "+f"(c[0]), "+f"(c[1]), "+f"(c[2]), "+f"(c[3])
                 : "r"(a[0]), "r"(a[1]), "r"(a[2]), "r"(a[3]), "r"(b0), "r"(b1));
}

template<int ROWB, int NKS>
__device__ __forceinline__ void gemm_core(uint32_t AHI, uint32_t ALO,
                                          uint32_t BHI, uint32_t BLO,
                                          int m0, int n0, int lane,
                                          float acc[2][8][4]) {
    int r = lane & 7, sub = lane >> 3;
    int aRow = (sub & 1) * 8 + r, aK = (sub >> 1) * 8;
    int bRow = (sub >> 1) * 8 + r, bK = (sub & 1) * 8;
#pragma unroll
    for (int ks = 0; ks < NKS; ks++) {
        int k0 = ks * 16;
        uint32_t ahi[2][4], alo[2][4];
#pragma unroll
        for (int am = 0; am < 2; am++) {
            uint32_t base = (uint32_t)((m0 + am * 16 + aRow) * ROWB + (k0 + aK) * 2);
            ldsm_x4(AHI + base, ahi[am][0], ahi[am][1], ahi[am][2], ahi[am][3]);
            ldsm_x4(ALO + base, alo[am][0], alo[am][1], alo[am][2], alo[am][3]);
        }
#pragma unroll
        for (int g = 0; g < 4; g++) {
            uint32_t base = (uint32_t)((n0 + g * 16 + bRow) * ROWB + (k0 + bK) * 2);
            uint32_t bh0, bh1, bh2, bh3, bl0, bl1, bl2, bl3;
            ldsm_x4(BHI + base, bh0, bh1, bh2, bh3);
            ldsm_x4(BLO + base, bl0, bl1, bl2, bl3);
#pragma unroll
            for (int am = 0; am < 2; am++) {
                mma16816(acc[am][g * 2 + 0], ahi[am], bh0, bh1);
                mma16816(acc[am][g * 2 + 1], ahi[am], bh2, bh3);
                mma16816(acc[am][g * 2 + 0], ahi[am], bl0, bl1);
                mma16816(acc[am][g * 2 + 1], ahi[am], bl2, bl3);
                mma16816(acc[am][g * 2 + 0], alo[am], bh0, bh1);
                mma16816(acc[am][g * 2 + 1], alo[am], bh2, bh3);
            }
        }
    }
}

__device__ __forceinline__ void zero_acc(float acc[2][8][4]) {
#pragma unroll
    for (int am = 0; am < 2; am++)
#pragma unroll
        for (int g = 0; g < 8; g++)
#pragma unroll
            for (int e = 0; e < 4; e++) acc[am][g][e] = 0.f;
}

__device__ __forceinline__ void epilogue(float acc[2][8][4], float* __restrict__ dst,
                                         bool mask, int m0, int n0, int lane) {
    int t4 = lane >> 2, tp2 = (lane & 3) * 2;
#pragma unroll
    for (int am = 0; am < 2; am++) {
#pragma unroll
        for (int g = 0; g < 8; g++) {
            int col = n0 + g * 8 + tp2;
            int row0 = m0 + am * 16 + t4;
            float c0 = acc[am][g][0], c1 = acc[am][g][1];
            float c2 = acc[am][g][2], c3 = acc[am][g][3];
            if (mask) {
                if (row0 < col)         c0 = 0.f;
                if (row0 < col + 1)     c1 = 0.f;
                if (row0 + 8 < col)     c2 = 0.f;
                if (row0 + 8 < col + 1) c3 = 0.f;
            }
            *(float2*)(dst + row0 * 128 + col)       = make_float2(c0, c1);
            *(float2*)(dst + (row0 + 8) * 128 + col) = make_float2(c2, c3);
        }
    }
}

// ---------------------------------------------------------------------------
// Power tables
// ---------------------------------------------------------------------------
__global__ void pow_kernel(const float* __restrict__ gamma) {
    int r = threadIdx.x, row = blockIdx.x;
    float lg = logf(gamma[r]);
    if (row < 129) g_ptab[row * 128 + r] = expf((float)row * lg);
    else           g_ntab[(row - 129) * 128 + r] = expf(-(float)(row - 129) * lg);
}

// ---------------------------------------------------------------------------
// Phase 1 (z=0): A = mask((QΓ)(KΓ')^T); (z=1): Ut[d,r]
// R12 structure: k32 double-buffered tiles, 1 sync/chunk, grid z=2
// ---------------------------------------------------------------------------
__global__ __launch_bounds__(NTHR, 2) void matAU_kernel(const float* __restrict__ q,
                                                        const float* __restrict__ k,
                                                        const float* __restrict__ h) {
    extern __shared__ __align__(16) char smem[];
    int n = blockIdx.x, b = blockIdx.y;
    int tid = threadIdx.x, wid = tid >> 5, lane = tid & 31;
    int m0 = (wid & 3) * 32, n0 = (wid >> 2) * 64;

    const int in_base = (b * Wdim + n * BLK) * Rdim;
    const bool zA = (blockIdx.z == 0);
    float acc[2][8][4];
    zero_acc(acc);

    if (zA) {
        stage_nat32(q + in_base, g_ptab, 0, 0, smem, smem + CTILEB32, tid);
        stage_nat32(k + in_base, g_ntab, 0, 0, smem + 2 * CTILEB32, smem + 3 * CTILEB32, tid);
    } else {
        stage_tr32(h + in_base, false, 0, smem, smem + CTILEB32, tid);
        stage_tr32(k + in_base, true,  0, smem + 2 * CTILEB32, smem + 3 * CTILEB32, tid);
    }
    __syncthreads();

#pragma unroll
    for (int c = 0; c < 4; c++) {
        char* cur = smem + (c & 1) * TILBUF32;
        uint32_t cb = smem_u32(cur);
        gemm_core<CROWB32, 2>(cb, cb + CTILEB32, cb + 2 * CTILEB32, cb + 3 * CTILEB32,
                              m0, n0, lane, acc);
        if (c + 1 < 4) {
            char* nxt = smem + ((c + 1) & 1) * TILBUF32;
            int kc = (c + 1) * 32;
            if (zA) {
                stage_nat32(q + in_base, g_ptab, 0, kc, nxt, nxt + CTILEB32, tid);
                stage_nat32(k + in_base, g_ntab, 0, kc, nxt + 2 * CTILEB32, nxt + 3 * CTILEB32, tid);
            } else {
                stage_tr32(h + in_base, false, kc, nxt, nxt + CTILEB32, tid);
                stage_tr32(k + in_base, true,  kc, nxt + 2 * CTILEB32, nxt + 3 * CTILEB32, tid);
            }
        }
        __syncthreads();
    }

    if (zA) epilogue(acc, g_A + (b * NBLK + n) * (BLK * BLK), true, m0, n0, lane);
    else    epilogue(acc, g_U + (b * NBLK + n) * (Ddim * Rdim), false, m0, n0, lane);
}

// ---------------------------------------------------------------------------
// Phase 2: prefix scan on [d][r] state, MLP-32 preload
// ---------------------------------------------------------------------------
__global__ void scan_kernel() {
    int gid = blockIdx.x * 256 + threadIdx.x;   // 131072
    int b = gid >> 14, dr = gid & 16383, r = dr & 127;
    float gdec = g_ptab[128 * 128 + r];         // gamma_r^128
    int base = b * NBLK * 16384 + dr;
    float u[NBLK];
#pragma unroll
    for (int nn = 0; nn < NBLK; nn++) u[nn] = g_U[base + nn * 16384];
    float s = 0.f;
#pragma unroll
    for (int nn = 0; nn < NBLK; nn++) {
        g_S[base + nn * 16384] = s;
        s = fmaf(s, gdec, u[nn]);
    }
}

// ---------------------------------------------------------------------------
// Phase 3: out = A @ H + (Q*g^(i+1)) @ St
// R8 structure: k64 chunks, single buffer, bulk-sync (measured best for this kernel)
// ---------------------------------------------------------------------------
__global__ __launch_bounds__(NTHR, 2) void out_kernel(const float* __restrict__ q,
                                                      const float* __restrict__ h,
                                                      float* __restrict__ out) {
    extern __shared__ __align__(16) char smem[];
    int n = blockIdx.x, b = blockIdx.y;
    int tid = threadIdx.x, wid = tid >> 5, lane = tid & 31;
    int m0 = (wid & 3) * 32, n0 = (wid >> 2) * 64;

    const float* Ablk = g_A + (b * NBLK + n) * (BLK * BLK);
    const float* Sblk = g_S + (b * NBLK + n) * (Ddim * Rdim);
    const float* hblk = h + (b * Wdim + n * BLK) * Ddim;
    const float* qblk = q + (b * Wdim + n * BLK) * Rdim;

    float acc[2][8][4];
    zero_acc(acc);
    uint32_t sb = smem_u32(smem);

    // part 1: A @ H (contraction j, 2 k64-chunks)
#pragma unroll
    for (int jc = 0; jc < 128; jc += 64) {
        stage_nat64(Ablk, (const float*)0, 0, jc, smem, smem + CTILEB64, tid);
        stage_tr64(hblk, false, jc, smem + 2 * CTILEB64, smem + 3 * CTILEB64, tid);
        __syncthreads();
        gemm_core<CROWB64, 4>(sb, sb + CTILEB64, sb + 2 * CTILEB64, sb + 3 * CTILEB64,
                              m0, n0, lane, acc);
        __syncthreads();
    }
    // part 2: (Q*g^(i+1)) @ St (contraction r, 2 k64-chunks)
#pragma unroll
    for (int rc = 0; rc < 128; rc += 64) {
        stage_nat64(qblk, g_ptab, 1, rc, smem, smem + CTILEB64, tid);
        stage_nat64(Sblk, (const float*)0, 0, rc, smem + 2 * CTILEB64, smem + 3 * CTILEB64, tid);
        __syncthreads();
        gemm_core<CROWB64, 4>(sb, sb + CTILEB64, sb + 2 * CTILEB64, sb + 3 * CTILEB64,
                              m0, n0, lane, acc);
        __syncthreads();
    }

    epilogue(acc, out + (b * Wdim + n * BLK) * Ddim, false, m0, n0, lane);
}

// ---------------------------------------------------------------------------
extern "C" void kernel_launch(void* const* d_in, const int* in_sizes, int n_in,
                              void* d_out, int out_size) {
    const float* q     = (const float*)d_in[0];
    const float* k     = (const float*)d_in[1];
    const float* h     = (const float*)d_in[2];
    const float* gamma = (const float*)d_in[3];
    float* out = (float*)d_out;

    cudaFuncSetAttribute(matAU_kernel, cudaFuncAttributeMaxDynamicSharedMemorySize, SMEM_AU);
    cudaFuncSetAttribute(out_kernel,   cudaFuncAttributeMaxDynamicSharedMemorySize, SMEM_OUT);

    pow_kernel<<<257, 128>>>(gamma);
    matAU_kernel<<<dim3(NBLK, Bdim, 2), NTHR, SMEM_AU>>>(q, k, h);
    scan_kernel<<<512, 256>>>();
    out_kernel<<<dim3(NBLK, Bdim), NTHR, SMEM_OUT>>>(q, h, out);
}

// round 16
// speedup vs baseline: 1.2353x; 1.2063x over previous
#include <cuda_runtime.h>
#include <cuda_bf16.h>
#include <cstdint>

#define Bdim 8
#define Wdim 4096
#define Rdim 128
#define Ddim 128
#define BLK  128
#define NBLK 32
#define NTHR 256

// ---------------------------------------------------------------------------
// Scratch (__device__ globals; allocation-free rule)
// ---------------------------------------------------------------------------
__device__ float g_ptab[129 * 128];   // ptab[i*128+r] = gamma_r^i
__device__ float g_ntab[128 * 128];   // ntab[j*128+r] = gamma_r^{-j}
__device__ float g_A[Bdim * NBLK * BLK * BLK];       // masked A[i][j]
__device__ float g_U[Bdim * NBLK * Ddim * Rdim];     // Ut layout [d][r]
__device__ float g_S[Bdim * NBLK * Ddim * Rdim];     // St layout [d][r]

// ---------------------------------------------------------------------------
// TF32 tile geometries (32-bit elements, 16B-aligned row strides):
//  k32 path (matAU): ROWB32=144 (32*4+16), tile 18432B, 2 ops x 2 bufs = 73728B
//  k64 path (out):   ROWB64=272 (64*4+16), tile 34816B, 2 ops           = 69632B
// Bank check: stride%128B -> rows rotate 4 banks; 8 ldsm rows cover all banks.
// ---------------------------------------------------------------------------
#define ROWB32    144
#define CTILEB32  (128 * ROWB32)           // 18432
#define TILBUF32  (2 * CTILEB32)           // 36864 (A tile + B tile)
#define SMEM_AU   (2 * TILBUF32)           // 73728 -> 2 CTAs/SM

#define ROWB64    272
#define CTILEB64  (128 * ROWB64)           // 34816
#define SMEM_OUT  (2 * CTILEB64)           // 69632 -> 2 CTAs/SM

__device__ __forceinline__ uint32_t smem_u32(const void* p) {
    uint32_t a;
    asm("{ .reg .u64 t; cvta.to.shared.u64 t, %1; cvt.u32.u64 %0, t; }" : "=r"(a) : "l"(p));
    return a;
}
__device__ __forceinline__ uint32_t f2tf32(float f) {
    uint32_t r;
    asm("cvt.rna.tf32.f32 %0, %1;" : "=r"(r) : "f"(f));
    return r;
}
__device__ __forceinline__ uint4 tf32x4(float4 v) {
    uint4 o;
    o.x = f2tf32(v.x); o.y = f2tf32(v.y); o.z = f2tf32(v.z); o.w = f2tf32(v.w);
    return o;
}

// ---------------------------------------------------------------------------
// k32 staging (matAU): gmem fp32 -> tf32 tile (rows x 32 k-cols)
// nat: tile[m][c] = src[m][kc+c] * (wt ? wt[(m+wrofs)*128 + kc+c] : 1)
// ---------------------------------------------------------------------------
__device__ __forceinline__ void stage_nat32(const float* __restrict__ src,
                                            const float* __restrict__ wt, int wrofs,
                                            int kc, char* tile, int tid) {
#pragma unroll
    for (int it = 0; it < 4; it++) {
        int t = tid + it * NTHR;            // 0..1023
        int row = t >> 3, c4 = (t & 7) << 2;
        float4 v = *(const float4*)(src + row * 128 + kc + c4);
        if (wt) {
            float4 w = *(const float4*)(wt + (row + wrofs) * 128 + kc + c4);
            v.x *= w.x; v.y *= w.y; v.z *= w.z; v.w *= w.w;
        }
        *(uint4*)(tile + row * ROWB32 + c4 * 4) = tf32x4(v);
    }
}
// tr: tile[c][j-jc] = src[j][c] * (useW ? ptab[(127-j)*128+c] : 1), j in [jc,jc+32)
__device__ __forceinline__ void stage_tr32(const float* __restrict__ src, bool useW,
                                           int jc, char* tile, int tid) {
    int jblk = tid >> 5, c0 = (tid & 31) << 2;   // 8 jblks x 32 c-groups
    uint32_t s[4][4];                            // [src row x][src col u]
#pragma unroll
    for (int x = 0; x < 4; x++) {
        int j = jc + jblk * 4 + x;
        float4 v = *(const float4*)(src + j * 128 + c0);
        if (useW) {
            float4 w = *(const float4*)(g_ptab + (127 - j) * 128 + c0);
            v.x *= w.x; v.y *= w.y; v.z *= w.z; v.w *= w.w;
        }
        uint4 p = tf32x4(v);
        s[x][0] = p.x; s[x][1] = p.y; s[x][2] = p.z; s[x][3] = p.w;
    }
#pragma unroll
    for (int u = 0; u < 4; u++) {
        uint4 o; o.x = s[0][u]; o.y = s[1][u]; o.z = s[2][u]; o.w = s[3][u];
        *(uint4*)(tile + (c0 + u) * ROWB32 + jblk * 16) = o;
    }
}

// ---------------------------------------------------------------------------
// k64 staging (out_kernel)
// ---------------------------------------------------------------------------
__device__ __forceinline__ void stage_nat64(const float* __restrict__ src,
                                            const float* __restrict__ wt, int wrofs,
                                            int kc, char* tile, int tid) {
#pragma unroll
    for (int it = 0; it < 8; it++) {
        int t = tid + it * NTHR;            // 0..2047
        int row = t >> 4, c4 = (t & 15) << 2;
        float4 v = *(const float4*)(src + row * 128 + kc + c4);
        if (wt) {
            float4 w = *(const float4*)(wt + (row + wrofs) * 128 + kc + c4);
            v.x *= w.x; v.y *= w.y; v.z *= w.z; v.w *= w.w;
        }
        *(uint4*)(tile + row * ROWB64 + c4 * 4) = tf32x4(v);
    }
}
__device__ __forceinline__ void stage_tr64(const float* __restrict__ src, bool useW,
                                           int jc, char* tile, int tid) {
#pragma unroll
    for (int it = 0; it < 2; it++) {
        int t = tid + it * NTHR;            // 0..511
        int jblk = t >> 5;                  // 0..15
        int c0   = (t & 31) << 2;           // 0..124
        uint32_t s[4][4];
#pragma unroll
        for (int x = 0; x < 4; x++) {
            int j = jc + jblk * 4 + x;
            float4 v = *(const float4*)(src + j * 128 + c0);
            if (useW) {
                float4 w = *(const float4*)(g_ptab + (127 - j) * 128 + c0);
                v.x *= w.x; v.y *= w.y; v.z *= w.z; v.w *= w.w;
            }
            uint4 p = tf32x4(v);
            s[x][0] = p.x; s[x][1] = p.y; s[x][2] = p.z; s[x][3] = p.w;
        }
#pragma unroll
        for (int u = 0; u < 4; u++) {
            uint4 o; o.x = s[0][u]; o.y = s[1][u]; o.z = s[2][u]; o.w = s[3][u];
            *(uint4*)(tile + (c0 + u) * ROWB64 + jblk * 16) = o;
        }
    }
}

// ---------------------------------------------------------------------------
// TF32 mma.sync core: 8 warps, warp tile 32x64
// Per k8 step: 2 A-ldsm + 4 B-ldsm, 16 mma.m16n8k8
// Fragment via ldmatrix.b16.x4: each 8x8 b16 matrix = 8x4 tf32 tile whose
// (row=lane/4, word=lane%4) distribution matches the tf32 fragment spec.
// ---------------------------------------------------------------------------
__device__ __forceinline__ void ldsm_x4(uint32_t addr, uint32_t& r0, uint32_t& r1,
                                        uint32_t& r2, uint32_t& r3) {
    asm volatile("ldmatrix.sync.aligned.m8n8.x4.shared.b16 {%0,%1,%2,%3}, [%4];"
                 : "=r"(r0), "=r"(r1), "=r"(r2), "=r"(r3) : "r"(addr));
}
__device__ __forceinline__ void mma_tf32(float* c, const uint32_t a[4],
                                         uint32_t b0, uint32_t b1) {
    asm volatile("mma.sync.aligned.m16n8k8.row.col.f32.tf32.tf32.f32 "
                 "{%0,%1,%2,%3}, {%4,%5,%6,%7}, {%8,%9}, {%0,%1,%2,%3};"
                 : "+f"(c[0]), "+f"(c[1]), "+f"(c[2]), "+f"(c[3])
                 : "r"(a[0]), "r"(a[1]), "r"(a[2]), "r"(a[3]), "r"(b0), "r"(b1));
}

template<int ROWB, int NK8>
__device__ __forceinline__ void gemm_tf32(uint32_t A, uint32_t B,
                                          int m0, int n0, int lane,
                                          float acc[2][8][4]) {
    int mrow = lane & 7;            // row within 8-row submatrix
    int midx = lane >> 3;           // which of 4 submatrices this thread addresses
    int dr  = (midx & 1) * 8;       // submatrix row offset
    int dk4 = (midx >> 1) * 4;      // submatrix k offset (tf32 cols)
#pragma unroll
    for (int ks = 0; ks < NK8; ks++) {
        int k0 = ks * 8;
        uint32_t a[2][4];
#pragma unroll
        for (int am = 0; am < 2; am++) {
            uint32_t addr = A + (uint32_t)((m0 + am * 16 + dr + mrow) * ROWB + (k0 + dk4) * 4);
            ldsm_x4(addr, a[am][0], a[am][1], a[am][2], a[am][3]);
        }
#pragma unroll
        for (int g = 0; g < 4; g++) {
            uint32_t addr = B + (uint32_t)((n0 + g * 16 + dr + mrow) * ROWB + (k0 + dk4) * 4);
            uint32_t b0, b1, b2, b3;   // b0=(n,k0) b1=(n+8,k0) b2=(n,k4) b3=(n+8,k4)
            ldsm_x4(addr, b0, b1, b2, b3);
#pragma unroll
            for (int am = 0; am < 2; am++) {
                mma_tf32(acc[am][g * 2 + 0], a[am], b0, b2);
                mma_tf32(acc[am][g * 2 + 1], a[am], b1, b3);
            }
        }
    }
}

__device__ __forceinline__ void zero_acc(float acc[2][8][4]) {
#pragma unroll
    for (int am = 0; am < 2; am++)
#pragma unroll
        for (int g = 0; g < 8; g++)
#pragma unroll
            for (int e = 0; e < 4; e++) acc[am][g][e] = 0.f;
}

__device__ __forceinline__ void epilogue(float acc[2][8][4], float* __restrict__ dst,
                                         bool mask, int m0, int n0, int lane) {
    int t4 = lane >> 2, tp2 = (lane & 3) * 2;
#pragma unroll
    for (int am = 0; am < 2; am++) {
#pragma unroll
        for (int g = 0; g < 8; g++) {
            int col = n0 + g * 8 + tp2;
            int row0 = m0 + am * 16 + t4;
            float c0 = acc[am][g][0], c1 = acc[am][g][1];
            float c2 = acc[am][g][2], c3 = acc[am][g][3];
            if (mask) {
                if (row0 < col)         c0 = 0.f;
                if (row0 < col + 1)     c1 = 0.f;
                if (row0 + 8 < col)     c2 = 0.f;
                if (row0 + 8 < col + 1) c3 = 0.f;
            }
            *(float2*)(dst + row0 * 128 + col)       = make_float2(c0, c1);
            *(float2*)(dst + (row0 + 8) * 128 + col) = make_float2(c2, c3);
        }
    }
}

// ---------------------------------------------------------------------------
// Power tables
// ---------------------------------------------------------------------------
__global__ void pow_kernel(const float* __restrict__ gamma) {
    int r = threadIdx.x, row = blockIdx.x;
    float lg = logf(gamma[r]);
    if (row < 129) g_ptab[row * 128 + r] = expf((float)row * lg);
    else           g_ntab[(row - 129) * 128 + r] = expf(-(float)(row - 129) * lg);
}

// ---------------------------------------------------------------------------
// Phase 1 (z=0): A = mask((QΓ)(KΓ')^T); (z=1): Ut[d,r]
// k32 double-buffered tf32 tiles, 1 sync/chunk, grid z=2
// ---------------------------------------------------------------------------
__global__ __launch_bounds__(NTHR, 2) void matAU_kernel(const float* __restrict__ q,
                                                        const float* __restrict__ k,
                                                        const float* __restrict__ h) {
    extern __shared__ __align__(16) char smem[];
    int n = blockIdx.x, b = blockIdx.y;
    int tid = threadIdx.x, wid = tid >> 5, lane = tid & 31;
    int m0 = (wid & 3) * 32, n0 = (wid >> 2) * 64;

    const int in_base = (b * Wdim + n * BLK) * Rdim;
    const bool zA = (blockIdx.z == 0);
    float acc[2][8][4];
    zero_acc(acc);

    if (zA) {
        stage_nat32(q + in_base, g_ptab, 0, 0, smem, tid);
        stage_nat32(k + in_base, g_ntab, 0, 0, smem + CTILEB32, tid);
    } else {
        stage_tr32(h + in_base, false, 0, smem, tid);
        stage_tr32(k + in_base, true,  0, smem + CTILEB32, tid);
    }
    __syncthreads();

#pragma unroll
    for (int c = 0; c < 4; c++) {
        uint32_t cb = smem_u32(smem + (c & 1) * TILBUF32);
        gemm_tf32<ROWB32, 4>(cb, cb + CTILEB32, m0, n0, lane, acc);
        if (c + 1 < 4) {
            char* nxt = smem + ((c + 1) & 1) * TILBUF32;
            int kc = (c + 1) * 32;
            if (zA) {
                stage_nat32(q + in_base, g_ptab, 0, kc, nxt, tid);
                stage_nat32(k + in_base, g_ntab, 0, kc, nxt + CTILEB32, tid);
            } else {
                stage_tr32(h + in_base, false, kc, nxt, tid);
                stage_tr32(k + in_base, true,  kc, nxt + CTILEB32, tid);
            }
        }
        __syncthreads();
    }

    if (zA) epilogue(acc, g_A + (b * NBLK + n) * (BLK * BLK), true, m0, n0, lane);
    else    epilogue(acc, g_U + (b * NBLK + n) * (Ddim * Rdim), false, m0, n0, lane);
}

// ---------------------------------------------------------------------------
// Phase 2: prefix scan on [d][r] state, MLP-32 preload
// ---------------------------------------------------------------------------
__global__ void scan_kernel() {
    int gid = blockIdx.x * 256 + threadIdx.x;   // 131072
    int b = gid >> 14, dr = gid & 16383, r = dr & 127;
    float gdec = g_ptab[128 * 128 + r];         // gamma_r^128
    int base = b * NBLK * 16384 + dr;
    float u[NBLK];
#pragma unroll
    for (int nn = 0; nn < NBLK; nn++) u[nn] = g_U[base + nn * 16384];
    float s = 0.f;
#pragma unroll
    for (int nn = 0; nn < NBLK; nn++) {
        g_S[base + nn * 16384] = s;
        s = fmaf(s, gdec, u[nn]);
    }
}

// ---------------------------------------------------------------------------
// Phase 3: out = A @ H + (Q*g^(i+1)) @ St
// k64 chunks, single buffer, bulk-sync (measured best structure for this kernel)
// ---------------------------------------------------------------------------
__global__ __launch_bounds__(NTHR, 2) void out_kernel(const float* __restrict__ q,
                                                      const float* __restrict__ h,
                                                      float* __restrict__ out) {
    extern __shared__ __align__(16) char smem[];
    int n = blockIdx.x, b = blockIdx.y;
    int tid = threadIdx.x, wid = tid >> 5, lane = tid & 31;
    int m0 = (wid & 3) * 32, n0 = (wid >> 2) * 64;

    const float* Ablk = g_A + (b * NBLK + n) * (BLK * BLK);
    const float* Sblk = g_S + (b * NBLK + n) * (Ddim * Rdim);
    const float* hblk = h + (b * Wdim + n * BLK) * Ddim;
    const float* qblk = q + (b * Wdim + n * BLK) * Rdim;

    float acc[2][8][4];
    zero_acc(acc);
    uint32_t sb = smem_u32(smem);

    // part 1: A @ H (contraction j, 2 k64-chunks)
#pragma unroll
    for (int jc = 0; jc < 128; jc += 64) {
        stage_nat64(Ablk, (const float*)0, 0, jc, smem, tid);
        stage_tr64(hblk, false, jc, smem + CTILEB64, tid);
        __syncthreads();
        gemm_tf32<ROWB64, 8>(sb, sb + CTILEB64, m0, n0, lane, acc);
        __syncthreads();
    }
    // part 2: (Q*g^(i+1)) @ St (contraction r, 2 k64-chunks)
#pragma unroll
    for (int rc = 0; rc < 128; rc += 64) {
        stage_nat64(qblk, g_ptab, 1, rc, smem, tid);
        stage_nat64(Sblk, (const float*)0, 0, rc, smem + CTILEB64, tid);
        __syncthreads();
        gemm_tf32<ROWB64, 8>(sb, sb + CTILEB64, m0, n0, lane, acc);
        __syncthreads();
    }

    epilogue(acc, out + (b * Wdim + n * BLK) * Ddim, false, m0, n0, lane);
}

// ---------------------------------------------------------------------------
extern "C" void kernel_launch(void* const* d_in, const int* in_sizes, int n_in,
                              void* d_out, int out_size) {
    const float* q     = (const float*)d_in[0];
    const float* k     = (const float*)d_in[1];
    const float* h     = (const float*)d_in[2];
    const float* gamma = (const float*)d_in[3];
    float* out = (float*)d_out;

    cudaFuncSetAttribute(matAU_kernel, cudaFuncAttributeMaxDynamicSharedMemorySize, SMEM_AU);
    cudaFuncSetAttribute(out_kernel,   cudaFuncAttributeMaxDynamicSharedMemorySize, SMEM_OUT);

    pow_kernel<<<257, 128>>>(gamma);
    matAU_kernel<<<dim3(NBLK, Bdim, 2), NTHR, SMEM_AU>>>(q, k, h);
    scan_kernel<<<512, 256>>>();
    out_kernel<<<dim3(NBLK, Bdim), NTHR, SMEM_OUT>>>(q, h, out);
}